// round 2
// baseline (speedup 1.0000x reference)
#include <cuda_runtime.h>
#include <math.h>

#define BATCH 4
#define SEQ 2048
#define DM 512
#define NH 8
#define HD 64
#define ROWS (BATCH*SEQ)
#define RPE_LEN (2*SEQ-1)

// Scratch (static __device__ — no allocations allowed)
__device__ float g_q[BATCH*NH*SEQ*HD];     // (b,h,s,d) 16MB
__device__ float g_k[BATCH*NH*SEQ*HD];
__device__ float g_v[BATCH*NH*SEQ*HD];
__device__ float g_o[BATCH*SEQ*DM];        // concat-head attention output
__device__ float g_sig[NH*RPE_LEN];        // sigmoid(rpe) per head
__device__ float g_scale[NH];              // exp(min(logit_scale, ln 100))

// ---------------------------------------------------------------------------
// Kernel 1: precompute sigmoid(rpe) table (head-major) and per-head scale
// ---------------------------------------------------------------------------
__global__ void prep_kernel(const float* __restrict__ rpe,
                            const float* __restrict__ ls) {
    int i = blockIdx.x * blockDim.x + threadIdx.x;
    if (i < NH * RPE_LEN) {
        int hh = i % NH;
        int p  = i / NH;
        float x = rpe[p * NH + hh];
        g_sig[hh * RPE_LEN + p] = 1.0f / (1.0f + __expf(-x));
    }
    if (i < NH) {
        g_scale[i] = __expf(fminf(ls[i], 4.6051701859880914f)); // ln(100)
    }
}

// ---------------------------------------------------------------------------
// Kernel 2: fused QKV projection.
// q[b,h,s,d] = sum_c query[b,s,c] * W[d*NH + h, c] + bias[d*NH + h]
// grid = (ROWS/64, NH, 3), block = 256, 64x64 tile, 4x4 per-thread micro.
// ---------------------------------------------------------------------------
__global__ __launch_bounds__(256) void qkv_kernel(
    const float* __restrict__ X,
    const float* __restrict__ Wq, const float* __restrict__ bq,
    const float* __restrict__ Wk, const float* __restrict__ bk,
    const float* __restrict__ Wv, const float* __restrict__ bv) {
    const int h     = blockIdx.y;
    const int which = blockIdx.z;
    const float* W    = (which == 0) ? Wq : (which == 1) ? Wk : Wv;
    const float* bias = (which == 0) ? bq : (which == 1) ? bk : bv;
    float* out        = (which == 0) ? g_q : (which == 1) ? g_k : g_v;

    const int row0 = blockIdx.x * 64;
    __shared__ float As[16][68];   // [k][m]
    __shared__ float Bs[16][68];   // [k][n]  (n = head-dim index d)

    const int tid = threadIdx.x;
    const int tx = tid & 15, ty = tid >> 4;
    const int lm = tid >> 2;          // 0..63
    const int lk = (tid & 3) * 4;     // 0,4,8,12

    float acc[4][4] = {};

    for (int k0 = 0; k0 < DM; k0 += 16) {
        float4 a = *(const float4*)(X + (row0 + lm) * DM + k0 + lk);
        As[lk + 0][lm] = a.x; As[lk + 1][lm] = a.y;
        As[lk + 2][lm] = a.z; As[lk + 3][lm] = a.w;
        float4 w4 = *(const float4*)(W + (lm * NH + h) * DM + k0 + lk);
        Bs[lk + 0][lm] = w4.x; Bs[lk + 1][lm] = w4.y;
        Bs[lk + 2][lm] = w4.z; Bs[lk + 3][lm] = w4.w;
        __syncthreads();
#pragma unroll
        for (int k = 0; k < 16; k++) {
            float4 av  = *(float4*)&As[k][ty * 4];
            float4 bv4 = *(float4*)&Bs[k][tx * 4];
            float aa[4] = {av.x, av.y, av.z, av.w};
            float bb[4] = {bv4.x, bv4.y, bv4.z, bv4.w};
#pragma unroll
            for (int i = 0; i < 4; i++)
#pragma unroll
                for (int j = 0; j < 4; j++)
                    acc[i][j] += aa[i] * bb[j];
        }
        __syncthreads();
    }

#pragma unroll
    for (int i = 0; i < 4; i++) {
        int r = row0 + ty * 4 + i;
        int b = r >> 11;            // /SEQ
        int s = r & (SEQ - 1);
        float4 o;
        o.x = acc[i][0] + bias[(tx * 4 + 0) * NH + h];
        o.y = acc[i][1] + bias[(tx * 4 + 1) * NH + h];
        o.z = acc[i][2] + bias[(tx * 4 + 2) * NH + h];
        o.w = acc[i][3] + bias[(tx * 4 + 3) * NH + h];
        *(float4*)(out + ((b * NH + h) * SEQ + s) * HD + tx * 4) = o;
    }
}

// ---------------------------------------------------------------------------
// Kernel 3: flash attention per (b,h). grid = (SEQ/64, BATCH*NH), block 256.
// Dynamic smem: Qt[64][68] (d-major), Kt[64][68] (d-major), Vs[64][68],
// Ps[64][68], sg[128]
// ---------------------------------------------------------------------------
#define ATTN_SMEM_FLOATS (4 * 64 * 68 + 128)
#define ATTN_SMEM_BYTES  (ATTN_SMEM_FLOATS * 4)

__global__ __launch_bounds__(256) void attn_kernel() {
    extern __shared__ float sm[];
    float* Qt = sm;                    // [d][row]
    float* Kt = sm + 1 * 64 * 68;      // [d][key]
    float* Vs = sm + 2 * 64 * 68;      // [key][d]
    float* Ps = sm + 3 * 64 * 68;      // [row][key]
    float* sg = sm + 4 * 64 * 68;      // [127]

    const int bh = blockIdx.y;
    const int b = bh >> 3, h = bh & 7;
    const float* Q = g_q + (size_t)bh * SEQ * HD;
    const float* K = g_k + (size_t)bh * SEQ * HD;
    const float* V = g_v + (size_t)bh * SEQ * HD;
    const int q0 = blockIdx.x * 64;

    const int tid = threadIdx.x;
    const int tx = tid & 15, ty = tid >> 4;
    const float cscale = g_scale[h] * 0.04419417382415922f;  // 1/sqrt(512)

    // Load Q tile transposed (d-major)
    for (int e = tid; e < 1024; e += 256) {
        int row = e >> 4;
        int dd  = (e & 15) * 4;
        float4 qv = *(const float4*)(Q + (q0 + row) * HD + dd);
        Qt[(dd + 0) * 68 + row] = qv.x;
        Qt[(dd + 1) * 68 + row] = qv.y;
        Qt[(dd + 2) * 68 + row] = qv.z;
        Qt[(dd + 3) * 68 + row] = qv.w;
    }

    float m[4], l[4], O[4][4];
#pragma unroll
    for (int i = 0; i < 4; i++) {
        m[i] = -1e30f; l[i] = 0.0f;
#pragma unroll
        for (int j = 0; j < 4; j++) O[i][j] = 0.0f;
    }

    for (int kt = 0; kt < 32; kt++) {
        const int k0 = kt * 64;
        // Load K (transposed) and V tiles
        for (int e = tid; e < 1024; e += 256) {
            int row = e >> 4;
            int dd  = (e & 15) * 4;
            float4 kv = *(const float4*)(K + (k0 + row) * HD + dd);
            Kt[(dd + 0) * 68 + row] = kv.x;
            Kt[(dd + 1) * 68 + row] = kv.y;
            Kt[(dd + 2) * 68 + row] = kv.z;
            Kt[(dd + 3) * 68 + row] = kv.w;
            float4 vv = *(const float4*)(V + (k0 + row) * HD + dd);
            *(float4*)&Vs[row * 68 + dd] = vv;
        }
        // RPE bias slice: idx = (q0+rq) - (k0+rk) + 2047 -> base + (rq-rk+63)
        for (int t = tid; t < 127; t += 256)
            sg[t] = g_sig[h * RPE_LEN + (q0 - k0 + 1984) + t];
        __syncthreads();

        // S = Q K^T  (4x4 per-thread micro over d)
        float sacc[4][4] = {};
#pragma unroll 8
        for (int d = 0; d < 64; d++) {
            float4 qv = *(float4*)&Qt[d * 68 + ty * 4];
            float4 kv = *(float4*)&Kt[d * 68 + tx * 4];
            float qq[4] = {qv.x, qv.y, qv.z, qv.w};
            float kk[4] = {kv.x, kv.y, kv.z, kv.w};
#pragma unroll
            for (int i = 0; i < 4; i++)
#pragma unroll
                for (int j = 0; j < 4; j++)
                    sacc[i][j] += qq[i] * kk[j];
        }

        // scale + bias, online softmax update (reduce across 16 tx lanes)
#pragma unroll
        for (int i = 0; i < 4; i++) {
            float pv[4];
            float rmax = -1e30f;
#pragma unroll
            for (int j = 0; j < 4; j++) {
                float sv = sacc[i][j] * cscale +
                           sg[(ty * 4 + i) - (tx * 4 + j) + 63];
                pv[j] = sv;
                rmax = fmaxf(rmax, sv);
            }
#pragma unroll
            for (int off = 8; off; off >>= 1)
                rmax = fmaxf(rmax, __shfl_xor_sync(0xffffffffu, rmax, off));
            float mnew  = fmaxf(m[i], rmax);
            float alpha = __expf(m[i] - mnew);
            float rsum = 0.0f;
#pragma unroll
            for (int j = 0; j < 4; j++) {
                pv[j] = __expf(pv[j] - mnew);
                rsum += pv[j];
            }
#pragma unroll
            for (int off = 8; off; off >>= 1)
                rsum += __shfl_xor_sync(0xffffffffu, rsum, off);
            l[i] = l[i] * alpha + rsum;
            m[i] = mnew;
#pragma unroll
            for (int j = 0; j < 4; j++) O[i][j] *= alpha;
            *(float4*)&Ps[(ty * 4 + i) * 68 + tx * 4] =
                make_float4(pv[0], pv[1], pv[2], pv[3]);
        }
        __syncthreads();

        // O += P V
#pragma unroll 8
        for (int k = 0; k < 64; k++) {
            float4 vv = *(float4*)&Vs[k * 68 + tx * 4];
#pragma unroll
            for (int i = 0; i < 4; i++) {
                float pp = Ps[(ty * 4 + i) * 68 + k];
                O[i][0] += pp * vv.x;
                O[i][1] += pp * vv.y;
                O[i][2] += pp * vv.z;
                O[i][3] += pp * vv.w;
            }
        }
        __syncthreads();
    }

    // Normalize and write to concat-head layout: col = h*64 + d
#pragma unroll
    for (int i = 0; i < 4; i++) {
        float inv = 1.0f / l[i];
        int s = q0 + ty * 4 + i;
        float4 o = make_float4(O[i][0] * inv, O[i][1] * inv,
                               O[i][2] * inv, O[i][3] * inv);
        *(float4*)(g_o + ((size_t)(b * SEQ + s)) * DM + h * HD + tx * 4) = o;
    }
}

// ---------------------------------------------------------------------------
// Kernel 4: output projection. out[r,j] = sum_c g_o[r,c]*Wp[j,c] + bp[j]
// grid = (ROWS/64, DM/64), block 256.
// ---------------------------------------------------------------------------
__global__ __launch_bounds__(256) void oproj_kernel(
    const float* __restrict__ Wp, const float* __restrict__ bp,
    float* __restrict__ out) {
    const int row0 = blockIdx.x * 64;
    const int n0   = blockIdx.y * 64;
    __shared__ float As[16][68];
    __shared__ float Bs[16][68];

    const int tid = threadIdx.x;
    const int tx = tid & 15, ty = tid >> 4;
    const int lm = tid >> 2;
    const int lk = (tid & 3) * 4;

    float acc[4][4] = {};

    for (int k0 = 0; k0 < DM; k0 += 16) {
        float4 a = *(const float4*)(g_o + (row0 + lm) * DM + k0 + lk);
        As[lk + 0][lm] = a.x; As[lk + 1][lm] = a.y;
        As[lk + 2][lm] = a.z; As[lk + 3][lm] = a.w;
        float4 w4 = *(const float4*)(Wp + (n0 + lm) * DM + k0 + lk);
        Bs[lk + 0][lm] = w4.x; Bs[lk + 1][lm] = w4.y;
        Bs[lk + 2][lm] = w4.z; Bs[lk + 3][lm] = w4.w;
        __syncthreads();
#pragma unroll
        for (int k = 0; k < 16; k++) {
            float4 av  = *(float4*)&As[k][ty * 4];
            float4 bv4 = *(float4*)&Bs[k][tx * 4];
            float aa[4] = {av.x, av.y, av.z, av.w};
            float bb[4] = {bv4.x, bv4.y, bv4.z, bv4.w};
#pragma unroll
            for (int i = 0; i < 4; i++)
#pragma unroll
                for (int j = 0; j < 4; j++)
                    acc[i][j] += aa[i] * bb[j];
        }
        __syncthreads();
    }

#pragma unroll
    for (int i = 0; i < 4; i++) {
        int r = row0 + ty * 4 + i;
        float4 o;
        o.x = acc[i][0] + bp[n0 + tx * 4 + 0];
        o.y = acc[i][1] + bp[n0 + tx * 4 + 1];
        o.z = acc[i][2] + bp[n0 + tx * 4 + 2];
        o.w = acc[i][3] + bp[n0 + tx * 4 + 3];
        *(float4*)(out + r * DM + n0 + tx * 4) = o;
    }
}

// ---------------------------------------------------------------------------
extern "C" void kernel_launch(void* const* d_in, const int* in_sizes, int n_in,
                              void* d_out, int out_size) {
    (void)in_sizes; (void)n_in; (void)out_size;
    const float* query = (const float*)d_in[0];
    const float* Wq = (const float*)d_in[1];
    const float* bq = (const float*)d_in[2];
    const float* Wk = (const float*)d_in[3];
    const float* bk = (const float*)d_in[4];
    const float* Wv = (const float*)d_in[5];
    const float* bv = (const float*)d_in[6];
    const float* Wp = (const float*)d_in[7];
    const float* bp = (const float*)d_in[8];
    const float* ls = (const float*)d_in[9];
    const float* rpe = (const float*)d_in[10];

    cudaFuncSetAttribute(attn_kernel,
                         cudaFuncAttributeMaxDynamicSharedMemorySize,
                         ATTN_SMEM_BYTES);

    prep_kernel<<<(NH * RPE_LEN + 255) / 256, 256>>>(rpe, ls);
    qkv_kernel<<<dim3(ROWS / 64, NH, 3), 256>>>(query, Wq, bq, Wk, bk, Wv, bv);
    attn_kernel<<<dim3(SEQ / 64, BATCH * NH), 256, ATTN_SMEM_BYTES>>>();
    oproj_kernel<<<dim3(ROWS / 64, DM / 64), 256>>>(Wp, bp, (float*)d_out);
}